// round 10
// baseline (speedup 1.0000x reference)
#include <cuda_runtime.h>

#define BB 4096
#define TT 512
#define FF 16
#define HH 256
#define OUT_LEN 64
#define ROWS 28
#define P2 7             // 14 rows per thread-half, packed as 7 f32x2 accumulators
#define GRID 147         // ceil(4096/28)
#define THREADS 512
#define HS 30            // padded row stride (floats), even -> 8B aligned

typedef unsigned long long u64;

// -------- packed weight scratch (static device arrays; no allocation) -----
// padded by 2*HH entries so the k+2/k+3 prefetch at the loop tail stays in-bounds
__device__ float4 g_encW4[(HH + 2) * HH];   // [k][u] -> (Wi, Wf, Wg, Wo)
__device__ float4 g_decW4[(HH + 2) * HH];
__device__ float4 g_encX4[FF * HH];         // [f][u]
__device__ float4 g_encB4[HH];
__device__ float4 g_decB4[HH];
__device__ float4 g_decX4[HH];              // dec_Wih is [4H,1]

__global__ void pack_weights(const float* __restrict__ encWih, const float* __restrict__ encWhh,
                             const float* __restrict__ encB,   const float* __restrict__ decWih,
                             const float* __restrict__ decWhh, const float* __restrict__ decB)
{
    int idx = blockIdx.x * blockDim.x + threadIdx.x;
    int k = idx >> 8, u = idx & 255;
    if (idx < HH * HH) {
        g_encW4[idx] = make_float4(encWhh[u * HH + k],            encWhh[(HH + u) * HH + k],
                                   encWhh[(2 * HH + u) * HH + k], encWhh[(3 * HH + u) * HH + k]);
        g_decW4[idx] = make_float4(decWhh[u * HH + k],            decWhh[(HH + u) * HH + k],
                                   decWhh[(2 * HH + u) * HH + k], decWhh[(3 * HH + u) * HH + k]);
    }
    if (idx < FF * HH) { // k == f (0..15)
        g_encX4[idx] = make_float4(encWih[u * FF + k],            encWih[(HH + u) * FF + k],
                                   encWih[(2 * HH + u) * FF + k], encWih[(3 * HH + u) * FF + k]);
    }
    if (idx < HH) {
        g_encB4[idx] = make_float4(encB[idx], encB[HH + idx], encB[2 * HH + idx], encB[3 * HH + idx]);
        g_decB4[idx] = make_float4(decB[idx], decB[HH + idx], decB[2 * HH + idx], decB[3 * HH + idx]);
        g_decX4[idx] = make_float4(decWih[idx], decWih[HH + idx], decWih[2 * HH + idx], decWih[3 * HH + idx]);
    }
}

// -------- packed f32x2 helpers --------
__device__ __forceinline__ u64 pack2(float lo, float hi) {
    u64 r; asm("mov.b64 %0, {%1, %2};" : "=l"(r) : "f"(lo), "f"(hi)); return r;
}
__device__ __forceinline__ void fma2(u64& d, u64 a, u64 b) {
    asm("fma.rn.f32x2 %0, %1, %2, %0;" : "+l"(d) : "l"(a), "l"(b));
}
__device__ __forceinline__ float2 unpack2(u64 v) {
    float2 r; asm("mov.b64 {%0, %1}, %2;" : "=f"(r.x), "=f"(r.y) : "l"(v)); return r;
}
__device__ __forceinline__ float tanh_fast(float x) {
    float r; asm("tanh.approx.f32 %0, %1;" : "=f"(r) : "f"(x)); return r;
}
__device__ __forceinline__ float sig_fast(float x) {
    return fmaf(0.5f, tanh_fast(0.5f * x), 0.5f);
}

// dynamic shared memory (~67 KB): double-buffered h and x
struct __align__(16) Smem {
    float h[2][HH][HS];    // h[buf][k][r]
    float xs[2][FF][HS];   // xs[buf][f][r]
    float prev[32];        // decoder prev output
    float wout[HH];
    float bout;
};

// One 2-k step of the gate GEMM; weights already in registers (wa, wb),
// hp/hq point at this thread-half's 7 packed rows for rows k, k+1 (broadcast LDS.64).
#define GATE_K2(wa, wb, hp, hq)                                                  \
    {                                                                            \
        u64 ai = pack2(wa.x, wa.x), af = pack2(wa.y, wa.y);                      \
        u64 ag = pack2(wa.z, wa.z), ao = pack2(wa.w, wa.w);                      \
        _Pragma("unroll")                                                        \
        for (int p = 0; p < P2; p++) {                                           \
            u64 hv = hp[p];                                                      \
            fma2(acc[p][0], hv, ai); fma2(acc[p][1], hv, af);                    \
            fma2(acc[p][2], hv, ag); fma2(acc[p][3], hv, ao);                    \
        }                                                                        \
        u64 bi = pack2(wb.x, wb.x), bf = pack2(wb.y, wb.y);                      \
        u64 bg = pack2(wb.z, wb.z), bo = pack2(wb.w, wb.w);                      \
        _Pragma("unroll")                                                        \
        for (int p = 0; p < P2; p++) {                                           \
            u64 hv = hq[p];                                                      \
            fma2(acc[p][0], hv, bi); fma2(acc[p][1], hv, bf);                    \
            fma2(acc[p][2], hv, bg); fma2(acc[p][3], hv, bo);                    \
        }                                                                        \
    }

// pointwise update writing the NEW h buffer (hw = &sm->h[nbuf][u][rb])
#define POINTWISE_UPDATE(hw)                                                     \
    _Pragma("unroll")                                                            \
    for (int p = 0; p < P2; p++) {                                               \
        float2 iv = unpack2(acc[p][0]), fv = unpack2(acc[p][1]);                 \
        float2 gv = unpack2(acc[p][2]), ov = unpack2(acc[p][3]);                 \
        {                                                                        \
            int rl = 2 * p;                                                      \
            c[rl] = sig_fast(fv.x) * c[rl] + sig_fast(iv.x) * tanh_fast(gv.x);   \
            (hw)[rl] = sig_fast(ov.x) * tanh_fast(c[rl]);                        \
        }                                                                        \
        {                                                                        \
            int rl = 2 * p + 1;                                                  \
            c[rl] = sig_fast(fv.y) * c[rl] + sig_fast(iv.y) * tanh_fast(gv.y);   \
            (hw)[rl] = sig_fast(ov.y) * tanh_fast(c[rl]);                        \
        }                                                                        \
    }

__global__ __launch_bounds__(THREADS, 1)
void lstm_kernel(const float* __restrict__ x, const float* __restrict__ Wout,
                 const float* __restrict__ boutp, float* __restrict__ out)
{
    extern __shared__ char smraw[];
    Smem* sm = (Smem*)smraw;

    const int tid  = threadIdx.x;
    const int u    = tid & 255;          // hidden unit owned by this thread
    const int half = tid >> 8;           // 0: rows 0..13, 1: rows 14..27
    const int rb   = half * 14;          // row base within the 28-row tile
    const int b0   = blockIdx.x * ROWS;  // batch tile base

    // x-stage thread mapping (threads 0..447): row r = tid>>4, feature f = tid&15
    const int xr = tid >> 4, xf = tid & 15;
    int xb = b0 + xr; if (xb >= BB) xb = BB - 1;       // clamp for partial last tile
    const size_t xbase = (size_t)xb * (TT * FF) + xf;  // + t*FF per step
    const bool xactive = (tid < FF * ROWS);

    if (half == 0) sm->wout[u] = Wout[u];
    if (tid == 0) sm->bout = boutp[0];
#pragma unroll
    for (int r = 0; r < 14; r++) sm->h[0][u][rb + r] = 0.0f;

    float c[14];
#pragma unroll
    for (int r = 0; r < 14; r++) c[r] = 0.0f;

    // pre-stage x(0) into xs[0]
    if (xactive) sm->xs[0][xf][xr] = x[xbase];

    // ================= encoder: 512 steps, ONE barrier per step =================
    for (int t = 0; t < TT; t++) {
        const int cb = t & 1, nb = cb ^ 1;
        // loads independent of SMEM — issued before the barrier
        float4 bb = g_encB4[u];
        float4 wA = g_encW4[u];
        float4 wB = g_encW4[HH + u];

        __syncthreads();   // orders: xs[cb] stores + h[cb] writes (from t-1) before reads

        // prefetch x(t+1) — latency hidden under the k-loop below
        float xv_next = 0.0f;
        if (xactive) {
            int tn = (t + 1 < TT) ? t + 1 : t;
            xv_next = x[xbase + (size_t)tn * FF];
        }

        u64 acc[P2][4];
        {
            u64 bi = pack2(bb.x, bb.x), bf = pack2(bb.y, bb.y);
            u64 bg = pack2(bb.z, bb.z), bo = pack2(bb.w, bb.w);
#pragma unroll
            for (int p = 0; p < P2; p++) { acc[p][0] = bi; acc[p][1] = bf; acc[p][2] = bg; acc[p][3] = bo; }
        }

        // x @ Wih^T contribution (K = 16)
#pragma unroll
        for (int f = 0; f < FF; f += 2) {
            float4 wa = g_encX4[f * HH + u];
            float4 wb = g_encX4[(f + 1) * HH + u];
            const u64* hp = (const u64*)&sm->xs[cb][f][rb];
            const u64* hq = (const u64*)&sm->xs[cb][f + 1][rb];
            GATE_K2(wa, wb, hp, hq);
        }

        // h @ Whh^T contribution (K = 256) — hot loop with 1-iter-ahead prefetch
        for (int k = 0; k < HH; k += 2) {
            float4 wa = wA, wb = wB;
            wA = g_encW4[(k + 2) * HH + u];   // padded: always in-bounds
            wB = g_encW4[(k + 3) * HH + u];
            const u64* hp = (const u64*)&sm->h[cb][k][rb];
            const u64* hq = (const u64*)&sm->h[cb][k + 1][rb];
            GATE_K2(wa, wb, hp, hq);
        }

        // stage x(t+1) into the other x buffer (no reader until after next barrier)
        if (xactive) sm->xs[nb][xf][xr] = xv_next;

        // pointwise gates + state update -> h[nb] (no reader until after next barrier)
        float* hw = &sm->h[nb][u][rb];
        POINTWISE_UPDATE(hw);
    }
    __syncthreads();
    if (tid < 32) sm->prev[tid] = 0.0f;
    __syncthreads();

    // ================= decoder: 64 steps =================
    // encoder left final h in h[TT & 1] == h[0]; step s reads h[s&1], writes h[(s+1)&1]
    for (int s = 0; s < OUT_LEN; s++) {
        const int cb = s & 1, nb = cb ^ 1;
        float4 bb  = g_decB4[u];
        float4 dxw = g_decX4[u];
        float4 wA = g_decW4[u];
        float4 wB = g_decW4[HH + u];

        u64 acc[P2][4];
        {
            u64 bi = pack2(bb.x, bb.x), bf = pack2(bb.y, bb.y);
            u64 bg = pack2(bb.z, bb.z), bo = pack2(bb.w, bb.w);
#pragma unroll
            for (int p = 0; p < P2; p++) { acc[p][0] = bi; acc[p][1] = bf; acc[p][2] = bg; acc[p][3] = bo; }
        }
        {   // scalar input contribution: prev * dec_Wih
            u64 wi = pack2(dxw.x, dxw.x), wf2 = pack2(dxw.y, dxw.y);
            u64 wg = pack2(dxw.z, dxw.z), wo  = pack2(dxw.w, dxw.w);
            const u64* pp = (const u64*)&sm->prev[rb];
#pragma unroll
            for (int p = 0; p < P2; p++) {
                u64 pv = pp[p];
                fma2(acc[p][0], pv, wi); fma2(acc[p][1], pv, wf2);
                fma2(acc[p][2], pv, wg); fma2(acc[p][3], pv, wo);
            }
        }
        for (int k = 0; k < HH; k += 2) {
            float4 wa = wA, wb = wB;
            wA = g_decW4[(k + 2) * HH + u];
            wB = g_decW4[(k + 3) * HH + u];
            const u64* hp = (const u64*)&sm->h[cb][k][rb];
            const u64* hq = (const u64*)&sm->h[cb][k + 1][rb];
            GATE_K2(wa, wb, hp, hq);
        }
        // no barrier needed here: writes go to h[nb], readers of h[cb] unaffected
        float* hw = &sm->h[nb][u][rb];
        POINTWISE_UPDATE(hw);
        __syncthreads();   // h[nb] complete before output reduction

        // output head: 16 warps reduce 28 rows (warp w: row w, and row 16+w for w<12)
        {
            int warp = tid >> 5, lane = tid & 31;
#pragma unroll
            for (int j = 0; j < 2; j++) {
                int r = warp + 16 * j;
                if (r < ROWS) {
                    float p = 0.0f;
#pragma unroll
                    for (int i = 0; i < 8; i++) {
                        int kk = lane + 32 * i;
                        p += sm->h[nb][kk][r] * sm->wout[kk];
                    }
#pragma unroll
                    for (int off = 16; off; off >>= 1) p += __shfl_xor_sync(0xffffffffu, p, off);
                    if (lane == 0) {
                        float val = p + sm->bout;
                        if (b0 + r < BB) out[(size_t)(b0 + r) * OUT_LEN + s] = val;
                        sm->prev[r] = val;
                    }
                }
            }
        }
        __syncthreads();   // prev stable before next step
    }
}

extern "C" void kernel_launch(void* const* d_in, const int* in_sizes, int n_in,
                              void* d_out, int out_size)
{
    const float* x      = (const float*)d_in[0];
    const float* encWih = (const float*)d_in[1];
    const float* encWhh = (const float*)d_in[2];
    const float* encB   = (const float*)d_in[3];
    const float* decWih = (const float*)d_in[4];
    const float* decWhh = (const float*)d_in[5];
    const float* decB   = (const float*)d_in[6];
    const float* Wout   = (const float*)d_in[7];
    const float* bout   = (const float*)d_in[8];
    float* out = (float*)d_out;

    pack_weights<<<(HH * HH + 255) / 256, 256>>>(encWih, encWhh, encB, decWih, decWhh, decB);

    // dynamic smem > 48KB opt-in (idempotent, capture-safe)
    static int smem_set = 0;
    if (!smem_set) {
        cudaFuncSetAttribute(lstm_kernel, cudaFuncAttributeMaxDynamicSharedMemorySize,
                             (int)sizeof(Smem));
        smem_set = 1;
    }
    lstm_kernel<<<GRID, THREADS, sizeof(Smem)>>>(x, Wout, bout, out);
}

// round 12
// speedup vs baseline: 1.6232x; 1.6232x over previous
#include <cuda_runtime.h>

#define BB 4096
#define TT 512
#define FF 16
#define HH 256
#define OUT_LEN 64
#define ROWS 28
#define P2 7             // 14 rows per thread-half = 7 f32x2 accumulators
#define GRID 147         // ceil(4096/28)
#define THREADS 512
#define HS 36            // padded row stride (floats): 144B -> 16B-aligned halves, 4-way store conflicts
// row r (0..27) -> float index within a row: half0 at 0..13, half1 at 16..29
#define RIDX(r) ((r) < 14 ? (r) : (r) + 2)

typedef unsigned long long u64;

// -------- packed weight scratch (static device arrays; no allocation) -----
// padded by 2*HH entries so the k+2/k+3 prefetch at the loop tail stays in-bounds
__device__ float4 g_encW4[(HH + 2) * HH];   // [k][u] -> (Wi, Wf, Wg, Wo)
__device__ float4 g_decW4[(HH + 2) * HH];
__device__ float4 g_encX4[FF * HH];         // [f][u]
__device__ float4 g_encB4[HH];
__device__ float4 g_decB4[HH];
__device__ float4 g_decX4[HH];              // dec_Wih is [4H,1]

__global__ void pack_weights(const float* __restrict__ encWih, const float* __restrict__ encWhh,
                             const float* __restrict__ encB,   const float* __restrict__ decWih,
                             const float* __restrict__ decWhh, const float* __restrict__ decB)
{
    int idx = blockIdx.x * blockDim.x + threadIdx.x;
    int k = idx >> 8, u = idx & 255;
    if (idx < HH * HH) {
        g_encW4[idx] = make_float4(encWhh[u * HH + k],            encWhh[(HH + u) * HH + k],
                                   encWhh[(2 * HH + u) * HH + k], encWhh[(3 * HH + u) * HH + k]);
        g_decW4[idx] = make_float4(decWhh[u * HH + k],            decWhh[(HH + u) * HH + k],
                                   decWhh[(2 * HH + u) * HH + k], decWhh[(3 * HH + u) * HH + k]);
    }
    if (idx < FF * HH) { // k == f (0..15)
        g_encX4[idx] = make_float4(encWih[u * FF + k],            encWih[(HH + u) * FF + k],
                                   encWih[(2 * HH + u) * FF + k], encWih[(3 * HH + u) * FF + k]);
    }
    if (idx < HH) {
        g_encB4[idx] = make_float4(encB[idx], encB[HH + idx], encB[2 * HH + idx], encB[3 * HH + idx]);
        g_decB4[idx] = make_float4(decB[idx], decB[HH + idx], decB[2 * HH + idx], decB[3 * HH + idx]);
        g_decX4[idx] = make_float4(decWih[idx], decWih[HH + idx], decWih[2 * HH + idx], decWih[3 * HH + idx]);
    }
}

// -------- packed f32x2 helpers --------
__device__ __forceinline__ u64 pack2(float lo, float hi) {
    u64 r; asm("mov.b64 %0, {%1, %2};" : "=l"(r) : "f"(lo), "f"(hi)); return r;
}
__device__ __forceinline__ void fma2(u64& d, u64 a, u64 b) {
    asm("fma.rn.f32x2 %0, %1, %2, %0;" : "+l"(d) : "l"(a), "l"(b));
}
__device__ __forceinline__ float2 unpack2(u64 v) {
    float2 r; asm("mov.b64 {%0, %1}, %2;" : "=f"(r.x), "=f"(r.y) : "l"(v)); return r;
}
__device__ __forceinline__ float tanh_fast(float x) {
    float r; asm("tanh.approx.f32 %0, %1;" : "=f"(r) : "f"(x)); return r;
}
__device__ __forceinline__ float sig_fast(float x) {
    return fmaf(0.5f, tanh_fast(0.5f * x), 0.5f);
}

// load 7 packed f32x2 row values from a 16B-aligned base: 3x LDS.128 + 1x LDS.64 (broadcast)
#define LOAD_H7(H, base)                                                         \
    {                                                                            \
        const ulonglong2* _p2 = (const ulonglong2*)(base);                       \
        ulonglong2 _a = _p2[0], _b = _p2[1], _c = _p2[2];                        \
        (H)[0] = _a.x; (H)[1] = _a.y; (H)[2] = _b.x; (H)[3] = _b.y;              \
        (H)[4] = _c.x; (H)[5] = _c.y; (H)[6] = ((const u64*)(base))[6];          \
    }

// One 2-k step of the gate GEMM; weights already in registers (wa, wb),
// ba/bb_ = 16B-aligned pointers to this thread-half's 7 packed rows for k, k+1.
#define GATE_K2(wa, wb, ba, bb_)                                                 \
    {                                                                            \
        u64 ai = pack2(wa.x, wa.x), af = pack2(wa.y, wa.y);                      \
        u64 ag = pack2(wa.z, wa.z), ao = pack2(wa.w, wa.w);                      \
        u64 HA[7]; LOAD_H7(HA, ba);                                              \
        _Pragma("unroll")                                                        \
        for (int p = 0; p < P2; p++) {                                           \
            u64 hv = HA[p];                                                      \
            fma2(acc[p][0], hv, ai); fma2(acc[p][1], hv, af);                    \
            fma2(acc[p][2], hv, ag); fma2(acc[p][3], hv, ao);                    \
        }                                                                        \
        u64 bi = pack2(wb.x, wb.x), bf = pack2(wb.y, wb.y);                      \
        u64 bg = pack2(wb.z, wb.z), bo = pack2(wb.w, wb.w);                      \
        u64 HB[7]; LOAD_H7(HB, bb_);                                             \
        _Pragma("unroll")                                                        \
        for (int p = 0; p < P2; p++) {                                           \
            u64 hv = HB[p];                                                      \
            fma2(acc[p][0], hv, bi); fma2(acc[p][1], hv, bf);                    \
            fma2(acc[p][2], hv, bg); fma2(acc[p][3], hv, bo);                    \
        }                                                                        \
    }

#define POINTWISE_UPDATE()                                                       \
    _Pragma("unroll")                                                            \
    for (int p = 0; p < P2; p++) {                                               \
        float2 iv = unpack2(acc[p][0]), fv = unpack2(acc[p][1]);                 \
        float2 gv = unpack2(acc[p][2]), ov = unpack2(acc[p][3]);                 \
        {                                                                        \
            int rl = 2 * p;                                                      \
            c[rl] = sig_fast(fv.x) * c[rl] + sig_fast(iv.x) * tanh_fast(gv.x);   \
            h_s[u][rb + rl] = sig_fast(ov.x) * tanh_fast(c[rl]);                 \
        }                                                                        \
        {                                                                        \
            int rl = 2 * p + 1;                                                  \
            c[rl] = sig_fast(fv.y) * c[rl] + sig_fast(iv.y) * tanh_fast(gv.y);   \
            h_s[u][rb + rl] = sig_fast(ov.y) * tanh_fast(c[rl]);                 \
        }                                                                        \
    }

__global__ __launch_bounds__(THREADS, 1)
void lstm_kernel(const float* __restrict__ x, const float* __restrict__ Wout,
                 const float* __restrict__ boutp, float* __restrict__ out)
{
    __shared__ __align__(16) float h_s[HH][HS];
    __shared__ __align__(16) float x_s[FF][HS];
    __shared__ __align__(16) float prev_s[HS];
    __shared__ float wout_s[HH];
    __shared__ float bout_s;

    const int tid  = threadIdx.x;
    const int u    = tid & 255;          // hidden unit owned by this thread
    const int half = tid >> 8;           // 0: rows 0..13, 1: rows 14..27
    const int rb   = half * 16;          // float-index base of this half's rows (16B aligned)
    const int b0   = blockIdx.x * ROWS;  // batch tile base

    if (half == 0) wout_s[u] = Wout[u];
    if (tid == 0) bout_s = boutp[0];
#pragma unroll
    for (int r = 0; r < 14; r++) h_s[u][rb + r] = 0.0f;

    float c[14];
#pragma unroll
    for (int r = 0; r < 14; r++) c[r] = 0.0f;

    // ================= encoder: 512 steps =================
    for (int t = 0; t < TT; t++) {
        // stage x_t tile (pre-barrier, as R8): x_s[f][RIDX(r)]
        if (tid < FF * ROWS) {
            int r = tid >> 4, f = tid & 15;
            int b = b0 + r; if (b >= BB) b = BB - 1;   // clamp for partial last tile
            x_s[f][RIDX(r)] = x[(size_t)b * (TT * FF) + t * FF + f];
        }
        // hoisted LDGs (no SMEM dependence — issue before the barrier)
        float4 bb = g_encB4[u];
        float4 wA = g_encW4[u];
        float4 wB = g_encW4[HH + u];
        __syncthreads();

        u64 acc[P2][4];
        {
            u64 bi = pack2(bb.x, bb.x), bf = pack2(bb.y, bb.y);
            u64 bg = pack2(bb.z, bb.z), bo = pack2(bb.w, bb.w);
#pragma unroll
            for (int p = 0; p < P2; p++) { acc[p][0] = bi; acc[p][1] = bf; acc[p][2] = bg; acc[p][3] = bo; }
        }

        // x @ Wih^T contribution (K = 16)
#pragma unroll
        for (int f = 0; f < FF; f += 2) {
            float4 wa = g_encX4[f * HH + u];
            float4 wb = g_encX4[(f + 1) * HH + u];
            GATE_K2(wa, wb, &x_s[f][rb], &x_s[f + 1][rb]);
        }

        // h @ Whh^T contribution (K = 256) — hot loop with 1-iter-ahead prefetch
        for (int k = 0; k < HH; k += 2) {
            float4 wa = wA, wb = wB;
            wA = g_encW4[(k + 2) * HH + u];   // padded: always in-bounds
            wB = g_encW4[(k + 3) * HH + u];
            GATE_K2(wa, wb, &h_s[k][rb], &h_s[k + 1][rb]);
        }
        __syncthreads();   // all reads of h_s / x_s done

        POINTWISE_UPDATE();
        // next iteration's barrier orders these writes before reads
    }
    __syncthreads();
    if (tid < HS) prev_s[tid] = 0.0f;
    __syncthreads();

    // ================= decoder: 64 steps =================
    for (int s = 0; s < OUT_LEN; s++) {
        float4 bb  = g_decB4[u];
        float4 dxw = g_decX4[u];
        float4 wA = g_decW4[u];
        float4 wB = g_decW4[HH + u];

        u64 acc[P2][4];
        {
            u64 bi = pack2(bb.x, bb.x), bf = pack2(bb.y, bb.y);
            u64 bg = pack2(bb.z, bb.z), bo = pack2(bb.w, bb.w);
#pragma unroll
            for (int p = 0; p < P2; p++) { acc[p][0] = bi; acc[p][1] = bf; acc[p][2] = bg; acc[p][3] = bo; }
        }
        {   // scalar input contribution: prev * dec_Wih
            u64 wi = pack2(dxw.x, dxw.x), wf2 = pack2(dxw.y, dxw.y);
            u64 wg = pack2(dxw.z, dxw.z), wo  = pack2(dxw.w, dxw.w);
            u64 PV[7]; LOAD_H7(PV, &prev_s[rb]);
#pragma unroll
            for (int p = 0; p < P2; p++) {
                u64 pv = PV[p];
                fma2(acc[p][0], pv, wi); fma2(acc[p][1], pv, wf2);
                fma2(acc[p][2], pv, wg); fma2(acc[p][3], pv, wo);
            }
        }
        for (int k = 0; k < HH; k += 2) {
            float4 wa = wA, wb = wB;
            wA = g_decW4[(k + 2) * HH + u];
            wB = g_decW4[(k + 3) * HH + u];
            GATE_K2(wa, wb, &h_s[k][rb], &h_s[k + 1][rb]);
        }
        __syncthreads();

        POINTWISE_UPDATE();
        __syncthreads();   // h_s complete before output reduction

        // output head: 16 warps reduce 28 rows (warp w: row w, and row 16+w for w<12)
        {
            int warp = tid >> 5, lane = tid & 31;
#pragma unroll
            for (int j = 0; j < 2; j++) {
                int r = warp + 16 * j;
                if (r < ROWS) {
                    int ri = RIDX(r);
                    float p = 0.0f;
#pragma unroll
                    for (int i = 0; i < 8; i++) {
                        int kk = lane + 32 * i;
                        p += h_s[kk][ri] * wout_s[kk];
                    }
#pragma unroll
                    for (int off = 16; off; off >>= 1) p += __shfl_xor_sync(0xffffffffu, p, off);
                    if (lane == 0) {
                        float val = p + bout_s;
                        if (b0 + r < BB) out[(size_t)(b0 + r) * OUT_LEN + s] = val;
                        prev_s[ri] = val;
                    }
                }
            }
        }
        __syncthreads();   // prev_s/h_s stable before next step
    }
}

extern "C" void kernel_launch(void* const* d_in, const int* in_sizes, int n_in,
                              void* d_out, int out_size)
{
    const float* x      = (const float*)d_in[0];
    const float* encWih = (const float*)d_in[1];
    const float* encWhh = (const float*)d_in[2];
    const float* encB   = (const float*)d_in[3];
    const float* decWih = (const float*)d_in[4];
    const float* decWhh = (const float*)d_in[5];
    const float* decB   = (const float*)d_in[6];
    const float* Wout   = (const float*)d_in[7];
    const float* bout   = (const float*)d_in[8];
    float* out = (float*)d_out;

    pack_weights<<<(HH * HH + 255) / 256, 256>>>(encWih, encWhh, encB, decWih, decWhh, decB);
    lstm_kernel<<<GRID, THREADS>>>(x, Wout, bout, out);
}

// round 15
// speedup vs baseline: 1.6557x; 1.0200x over previous
#include <cuda_runtime.h>

#define BB 4096
#define TT 512
#define FF 16
#define HH 256
#define OUT_LEN 64
#define ROWS 14          // batch rows per CTA
#define P2 7             // 14 rows = 7 f32x2 accumulators per gate
#define GRID 293         // ceil(4096/14); 148 SMs x 2 CTAs = 296 slots -> single wave
#define THREADS 256
#define HS 20            // row stride (floats): 80B -> 16B-aligned rows, 4-way store conflicts

typedef unsigned long long u64;

// -------- packed weight scratch (static device arrays; no allocation) -----
// padded by 2*HH entries so the k+2/k+3 prefetch at the loop tail stays in-bounds
__device__ float4 g_encW4[(HH + 2) * HH];   // [k][u] -> (Wi, Wf, Wg, Wo)
__device__ float4 g_decW4[(HH + 2) * HH];
__device__ float4 g_encX4[FF * HH];         // [f][u]
__device__ float4 g_encB4[HH];
__device__ float4 g_decB4[HH];
__device__ float4 g_decX4[HH];              // dec_Wih is [4H,1]

__global__ void pack_weights(const float* __restrict__ encWih, const float* __restrict__ encWhh,
                             const float* __restrict__ encB,   const float* __restrict__ decWih,
                             const float* __restrict__ decWhh, const float* __restrict__ decB)
{
    int idx = blockIdx.x * blockDim.x + threadIdx.x;
    int k = idx >> 8, u = idx & 255;
    if (idx < HH * HH) {
        g_encW4[idx] = make_float4(encWhh[u * HH + k],            encWhh[(HH + u) * HH + k],
                                   encWhh[(2 * HH + u) * HH + k], encWhh[(3 * HH + u) * HH + k]);
        g_decW4[idx] = make_float4(decWhh[u * HH + k],            decWhh[(HH + u) * HH + k],
                                   decWhh[(2 * HH + u) * HH + k], decWhh[(3 * HH + u) * HH + k]);
    }
    if (idx < FF * HH) { // k == f (0..15)
        g_encX4[idx] = make_float4(encWih[u * FF + k],            encWih[(HH + u) * FF + k],
                                   encWih[(2 * HH + u) * FF + k], encWih[(3 * HH + u) * FF + k]);
    }
    if (idx < HH) {
        g_encB4[idx] = make_float4(encB[idx], encB[HH + idx], encB[2 * HH + idx], encB[3 * HH + idx]);
        g_decB4[idx] = make_float4(decB[idx], decB[HH + idx], decB[2 * HH + idx], decB[3 * HH + idx]);
        g_decX4[idx] = make_float4(decWih[idx], decWih[HH + idx], decWih[2 * HH + idx], decWih[3 * HH + idx]);
    }
}

// -------- packed f32x2 helpers --------
__device__ __forceinline__ u64 pack2(float lo, float hi) {
    u64 r; asm("mov.b64 %0, {%1, %2};" : "=l"(r) : "f"(lo), "f"(hi)); return r;
}
__device__ __forceinline__ void fma2(u64& d, u64 a, u64 b) {
    asm("fma.rn.f32x2 %0, %1, %2, %0;" : "+l"(d) : "l"(a), "l"(b));
}
__device__ __forceinline__ float2 unpack2(u64 v) {
    float2 r; asm("mov.b64 {%0, %1}, %2;" : "=f"(r.x), "=f"(r.y) : "l"(v)); return r;
}
__device__ __forceinline__ float tanh_fast(float x) {
    float r; asm("tanh.approx.f32 %0, %1;" : "=f"(r) : "f"(x)); return r;
}
__device__ __forceinline__ float sig_fast(float x) {
    return fmaf(0.5f, tanh_fast(0.5f * x), 0.5f);
}

// load 7 packed f32x2 row values from a 16B-aligned base: 3x LDS.128 + 1x LDS.64 (broadcast)
#define LOAD_H7(H, base)                                                         \
    {                                                                            \
        const ulonglong2* _p2 = (const ulonglong2*)(base);                       \
        ulonglong2 _a = _p2[0], _b = _p2[1], _c = _p2[2];                        \
        (H)[0] = _a.x; (H)[1] = _a.y; (H)[2] = _b.x; (H)[3] = _b.y;              \
        (H)[4] = _c.x; (H)[5] = _c.y; (H)[6] = ((const u64*)(base))[6];          \
    }

// One 2-k step of the gate GEMM; weights already in registers (wa, wb),
// ba/bb_ = 16B-aligned pointers to the 7 packed rows for k, k+1.
#define GATE_K2(wa, wb, ba, bb_)                                                 \
    {                                                                            \
        u64 ai = pack2(wa.x, wa.x), af = pack2(wa.y, wa.y);                      \
        u64 ag = pack2(wa.z, wa.z), ao = pack2(wa.w, wa.w);                      \
        u64 HA[7]; LOAD_H7(HA, ba);                                              \
        _Pragma("unroll")                                                        \
        for (int p = 0; p < P2; p++) {                                           \
            u64 hv = HA[p];                                                      \
            fma2(acc[p][0], hv, ai); fma2(acc[p][1], hv, af);                    \
            fma2(acc[p][2], hv, ag); fma2(acc[p][3], hv, ao);                    \
        }                                                                        \
        u64 bi = pack2(wb.x, wb.x), bf = pack2(wb.y, wb.y);                      \
        u64 bg = pack2(wb.z, wb.z), bo = pack2(wb.w, wb.w);                      \
        u64 HB[7]; LOAD_H7(HB, bb_);                                             \
        _Pragma("unroll")                                                        \
        for (int p = 0; p < P2; p++) {                                           \
            u64 hv = HB[p];                                                      \
            fma2(acc[p][0], hv, bi); fma2(acc[p][1], hv, bf);                    \
            fma2(acc[p][2], hv, bg); fma2(acc[p][3], hv, bo);                    \
        }                                                                        \
    }

#define POINTWISE_UPDATE()                                                       \
    _Pragma("unroll")                                                            \
    for (int p = 0; p < P2; p++) {                                               \
        float2 iv = unpack2(acc[p][0]), fv = unpack2(acc[p][1]);                 \
        float2 gv = unpack2(acc[p][2]), ov = unpack2(acc[p][3]);                 \
        {                                                                        \
            int rl = 2 * p;                                                      \
            c[rl] = sig_fast(fv.x) * c[rl] + sig_fast(iv.x) * tanh_fast(gv.x);   \
            h_s[u][rl] = sig_fast(ov.x) * tanh_fast(c[rl]);                      \
        }                                                                        \
        {                                                                        \
            int rl = 2 * p + 1;                                                  \
            c[rl] = sig_fast(fv.y) * c[rl] + sig_fast(iv.y) * tanh_fast(gv.y);   \
            h_s[u][rl] = sig_fast(ov.y) * tanh_fast(c[rl]);                      \
        }                                                                        \
    }

__global__ __launch_bounds__(THREADS, 2)
void lstm_kernel(const float* __restrict__ x, const float* __restrict__ Wout,
                 const float* __restrict__ boutp, float* __restrict__ out)
{
    __shared__ __align__(16) float h_s[HH][HS];
    __shared__ __align__(16) float x_s[FF][HS];
    __shared__ __align__(16) float prev_s[HS];
    __shared__ float wout_s[HH];
    __shared__ float bout_s;

    const int u  = threadIdx.x;          // hidden unit owned by this thread
    const int b0 = blockIdx.x * ROWS;    // batch tile base

    wout_s[u] = Wout[u];
    if (u == 0) bout_s = boutp[0];
#pragma unroll
    for (int r = 0; r < ROWS; r++) h_s[u][r] = 0.0f;

    float c[ROWS];
#pragma unroll
    for (int r = 0; r < ROWS; r++) c[r] = 0.0f;

    // ================= encoder: 512 steps =================
    for (int t = 0; t < TT; t++) {
        // stage x_t tile (pre-barrier): x_s[f][r]; threads 0..223 active
        if (u < FF * ROWS) {
            int r = u >> 4, f = u & 15;
            int b = b0 + r; if (b >= BB) b = BB - 1;   // clamp for partial last tile
            x_s[f][r] = x[(size_t)b * (TT * FF) + t * FF + f];
        }
        // hoisted LDGs (no SMEM dependence — issue before the barrier)
        float4 bb = g_encB4[u];
        float4 wA = g_encW4[u];
        float4 wB = g_encW4[HH + u];
        __syncthreads();

        u64 acc[P2][4];
        {
            u64 bi = pack2(bb.x, bb.x), bf = pack2(bb.y, bb.y);
            u64 bg = pack2(bb.z, bb.z), bo = pack2(bb.w, bb.w);
#pragma unroll
            for (int p = 0; p < P2; p++) { acc[p][0] = bi; acc[p][1] = bf; acc[p][2] = bg; acc[p][3] = bo; }
        }

        // x @ Wih^T contribution (K = 16)
#pragma unroll
        for (int f = 0; f < FF; f += 2) {
            float4 wa = g_encX4[f * HH + u];
            float4 wb = g_encX4[(f + 1) * HH + u];
            GATE_K2(wa, wb, &x_s[f][0], &x_s[f + 1][0]);
        }

        // h @ Whh^T contribution (K = 256) — hot loop with 1-iter-ahead prefetch
        for (int k = 0; k < HH; k += 2) {
            float4 wa = wA, wb = wB;
            wA = g_encW4[(k + 2) * HH + u];   // padded: always in-bounds
            wB = g_encW4[(k + 3) * HH + u];
            GATE_K2(wa, wb, &h_s[k][0], &h_s[k + 1][0]);
        }
        __syncthreads();   // all reads of h_s / x_s done

        POINTWISE_UPDATE();
        // next iteration's barrier orders these writes before reads
    }
    __syncthreads();
    if (u < HS) prev_s[u] = 0.0f;
    __syncthreads();

    // ================= decoder: 64 steps =================
    for (int s = 0; s < OUT_LEN; s++) {
        float4 bb  = g_decB4[u];
        float4 dxw = g_decX4[u];
        float4 wA = g_decW4[u];
        float4 wB = g_decW4[HH + u];

        u64 acc[P2][4];
        {
            u64 bi = pack2(bb.x, bb.x), bf = pack2(bb.y, bb.y);
            u64 bg = pack2(bb.z, bb.z), bo = pack2(bb.w, bb.w);
#pragma unroll
            for (int p = 0; p < P2; p++) { acc[p][0] = bi; acc[p][1] = bf; acc[p][2] = bg; acc[p][3] = bo; }
        }
        {   // scalar input contribution: prev * dec_Wih
            u64 wi = pack2(dxw.x, dxw.x), wf2 = pack2(dxw.y, dxw.y);
            u64 wg = pack2(dxw.z, dxw.z), wo  = pack2(dxw.w, dxw.w);
            u64 PV[7]; LOAD_H7(PV, &prev_s[0]);
#pragma unroll
            for (int p = 0; p < P2; p++) {
                u64 pv = PV[p];
                fma2(acc[p][0], pv, wi); fma2(acc[p][1], pv, wf2);
                fma2(acc[p][2], pv, wg); fma2(acc[p][3], pv, wo);
            }
        }
        for (int k = 0; k < HH; k += 2) {
            float4 wa = wA, wb = wB;
            wA = g_decW4[(k + 2) * HH + u];
            wB = g_decW4[(k + 3) * HH + u];
            GATE_K2(wa, wb, &h_s[k][0], &h_s[k + 1][0]);
        }
        __syncthreads();

        POINTWISE_UPDATE();
        __syncthreads();   // h_s complete before output reduction

        // output head: 8 warps reduce 14 rows (warp w: row w, and row 8+w for w<6)
        {
            int warp = u >> 5, lane = u & 31;
#pragma unroll
            for (int j = 0; j < 2; j++) {
                int r = warp + 8 * j;
                if (r < ROWS) {
                    float p = 0.0f;
#pragma unroll
                    for (int i = 0; i < 8; i++) {
                        int kk = lane + 32 * i;
                        p += h_s[kk][r] * wout_s[kk];
                    }
#pragma unroll
                    for (int off = 16; off; off >>= 1) p += __shfl_xor_sync(0xffffffffu, p, off);
                    if (lane == 0) {
                        float val = p + bout_s;
                        if (b0 + r < BB) out[(size_t)(b0 + r) * OUT_LEN + s] = val;
                        prev_s[r] = val;
                    }
                }
            }
        }
        __syncthreads();   // prev_s/h_s stable before next step
    }
}

extern "C" void kernel_launch(void* const* d_in, const int* in_sizes, int n_in,
                              void* d_out, int out_size)
{
    const float* x      = (const float*)d_in[0];
    const float* encWih = (const float*)d_in[1];
    const float* encWhh = (const float*)d_in[2];
    const float* encB   = (const float*)d_in[3];
    const float* decWih = (const float*)d_in[4];
    const float* decWhh = (const float*)d_in[5];
    const float* decB   = (const float*)d_in[6];
    const float* Wout   = (const float*)d_in[7];
    const float* bout   = (const float*)d_in[8];
    float* out = (float*)d_out;

    pack_weights<<<(HH * HH + 255) / 256, 256>>>(encWih, encWhh, encB, decWih, decWhh, decB);
    lstm_kernel<<<GRID, THREADS>>>(x, Wout, bout, out);
}